// round 7
// baseline (speedup 1.0000x reference)
#include <cuda_runtime.h>
#include <math.h>

#define NN    50000
#define FI    20
#define HIDD  500
#define NOUT  2
#define NPAIR 210            // upper-triangular (incl. diag) pairs of 20
#define BN_EPS 1e-5f
#define CH    250            // rows per block in k_tail2
#define NB    (NN / CH)      // 200 blocks (co-resident: 200 <= 148*2)

// ---- scratch (__device__ globals, zero-initialized; self-cleaning) ----
static __device__ int    g_deg[NN];            // edge count (self-loop in prepX)
static __device__ float  g_dinv[NN];
static __device__ float4 g_Xs4[NN * 5];        // Xs = dinv[n] * X[n]
static __device__ float4 g_P4[NN * 5];         // P[c] = sum_{r->c} Xs[r]
static __device__ double g_m[FI];              // column sums of aggX
static __device__ double g_G[NPAIR];           // upper-tri Gram aggX^T aggX
static __device__ int    g_c1;                 // arrival counter (reset each call)
static __device__ int    g_c2;                 // cleanup counter (reset each call)

// K1: in-degree histogram over col (int4 loads)
__global__ void __launch_bounds__(256) k_deg(const int* __restrict__ col, int E) {
    int t = blockIdx.x * blockDim.x + threadIdx.x;
    int e = 4 * t;
    if (e + 3 < E) {
        int4 c = *(const int4*)(col + e);
        atomicAdd(&g_deg[c.x], 1);
        atomicAdd(&g_deg[c.y], 1);
        atomicAdd(&g_deg[c.z], 1);
        atomicAdd(&g_deg[c.w], 1);
    } else {
        for (int k = e; k < E; k++) atomicAdd(&g_deg[col[k]], 1);
    }
}

// K2: dinv = rsqrt(cnt+1); Xs[n] = dinv[n]*X[n]; reset g_deg (self-clean)
__global__ void __launch_bounds__(256) k_prepX(const float* __restrict__ X) {
    int n = blockIdx.x * blockDim.x + threadIdx.x;
    if (n >= NN) return;
    float d = rsqrtf((float)(g_deg[n] + 1));
    g_deg[n] = 0;
    g_dinv[n] = d;
    const float4* xr = (const float4*)(X + n * FI);
#pragma unroll
    for (int k = 0; k < 5; k++) {
        float4 v = xr[k];
        v.x *= d; v.y *= d; v.z *= d; v.w *= d;
        g_Xs4[n * 5 + k] = v;
    }
}

// K3: edge scatter: P[c] += Xs[r]   (5x red.global.add.v4.f32 per edge)
__global__ void __launch_bounds__(256) k_scatter(const int* __restrict__ ei, int E) {
    int e = blockIdx.x * blockDim.x + threadIdx.x;
    if (e >= E) return;
    int r = ei[e];
    int c = ei[E + e];
    const float4* __restrict__ src = g_Xs4 + r * 5;
    float4* dst = g_P4 + c * 5;
#pragma unroll
    for (int k = 0; k < 5; k++) {
        float4 v = __ldg(src + k);
        asm volatile("red.global.add.v4.f32 [%0], {%1, %2, %3, %4};"
                     :: "l"(dst + k), "f"(v.x), "f"(v.y), "f"(v.z), "f"(v.w)
                     : "memory");
    }
}

// K4 (persistent, 200 co-resident blocks): stats -> arrival barrier ->
//     REDUNDANT prep in every block (no release wait) -> final.
//     aggX never touches global memory.
__global__ void __launch_bounds__(256, 2) k_tail2(
                       const float* __restrict__ W,      // gcn_W  [20,500]
                       const float* __restrict__ b,      // gcn_b  [500]
                       const float* __restrict__ gamma,  // [500]
                       const float* __restrict__ beta,   // [500]
                       const float* __restrict__ W2,     // lin_W  [500,2]
                       const float* __restrict__ lb,     // lin_b  [2]
                       float* __restrict__ out) {        // [NN*2 | 500 rsu]
    __shared__ float  s[CH * FI];        // 20 KB: this block's aggX chunk
    __shared__ float  sS[HIDD], sT[HIDD];
    __shared__ float  sGf[NPAIR];
    __shared__ double smm[FI];
    __shared__ float  sRed[42 * 6];
    __shared__ float  sMC[FI * NOUT + NOUT];
    int t = threadIdx.x;                 // 256 threads
    int bid = blockIdx.x;
    int n0 = bid * CH;

    // ---- Phase A: finalize chunk aggX = dinv*(P+Xs) into shared; zero P4
    for (int k = t; k < CH * 5; k += 256) {
        int n = n0 + k / 5;
        int idx = n * 5 + (k % 5);
        float d = g_dinv[n];
        float4 p = g_P4[idx];
        float4 x = g_Xs4[idx];
        float4 a = make_float4(d * (p.x + x.x), d * (p.y + x.y),
                               d * (p.z + x.z), d * (p.w + x.w));
        g_P4[idx] = make_float4(0.f, 0.f, 0.f, 0.f);   // self-clean
        ((float4*)s)[k] = a;
    }
    __syncthreads();

    // ---- Phase B: fp32 stat partials, double-atomic combine
    if (t < FI) {
        float a0 = 0.f, a1 = 0.f;
        for (int n = 0; n < CH; n += 2) {
            a0 += s[n * FI + t];
            a1 += s[(n + 1) * FI + t];
        }
        atomicAdd(&g_m[t], (double)(a0 + a1));
    } else if (t < FI + NPAIR) {
        int p = t - FI, i = 0;
        while (p >= FI - i) { p -= FI - i; i++; }
        int j = i + p;
        float a0 = 0.f, a1 = 0.f;
        for (int n = 0; n < CH; n += 2) {
            a0 += s[n * FI + i] * s[n * FI + j];
            a1 += s[(n + 1) * FI + i] * s[(n + 1) * FI + j];
        }
        atomicAdd(&g_G[t - FI], (double)(a0 + a1));
    }
    __syncthreads();

    // ---- Arrival barrier: one RMW arrival per block; PLAIN-LOAD polling
    if (t == 0) {
        __threadfence();
        atomicAdd(&g_c1, 1);
        while (*((volatile int*)&g_c1) < NB) { }
    }
    __syncthreads();
    __threadfence();                     // acquire: stats now visible

    // ---- Stage stats to shared (every block), then cleanup by last arriver
    if (t < FI)                   smm[t] = g_m[t];
    else if (t < FI + NPAIR)      sGf[t - FI] = (float)g_G[t - FI];
    __syncthreads();
    if (t == 0) {
        int v = atomicAdd(&g_c2, 1);
        if (v == NB - 1) {               // all blocks have read: safe to zero
            for (int k = 0; k < FI; k++)    g_m[k] = 0.0;
            for (int k = 0; k < NPAIR; k++) g_G[k] = 0.0;
            g_c1 = 0;
            g_c2 = 0;
            __threadfence();
        }
    }

    // ---- Redundant prep (every block, parallel): BN fold -> sS/sT
    for (int f = t; f < HIDD; f += 256) {
        float w[FI];
#pragma unroll
        for (int i2 = 0; i2 < FI; i2++) w[i2] = W[i2 * HIDD + f];
        float bf = b[f];
        double su = 0.0;
#pragma unroll
        for (int i2 = 0; i2 < FI; i2++) su += smm[i2] * (double)w[i2];
        float suf = (float)su;
        float mean = (suf + (float)NN * bf) * (1.f / (float)NN);
        float q = 0.f;
        int p = 0;
#pragma unroll
        for (int i2 = 0; i2 < FI; i2++) {
            q += sGf[p++] * w[i2] * w[i2];
#pragma unroll
            for (int j2 = i2 + 1; j2 < FI; j2++)
                q += 2.f * sGf[p++] * w[i2] * w[j2];
        }
        float sumsq_over_n = q * (1.f / (float)NN)
                           + 2.f * bf * suf * (1.f / (float)NN) + bf * bf;
        float var = sumsq_over_n - mean * mean;
        float sc = gamma[f] * rsqrtf(var + BN_EPS);
        float tt = beta[f] - mean * sc;
        sS[f] = sc; sT[f] = tt;
        if (bid == 0) {                  // rsu_embedding: node 0 row in s[0..19]
            float u0 = 0.f;
#pragma unroll
            for (int i2 = 0; i2 < FI; i2++) u0 += s[i2] * w[i2];
            out[NN * NOUT + f] = (u0 + bf) * sc + tt;
        }
    }
    __syncthreads();

    // ---- Fold M2/C locally: 42 outputs x 6 partial threads
    if (t < 42 * 6) {
        int o = t / 6, part = t % 6;
        int f0 = part * 84;
        int f1 = (f0 + 84 < HIDD) ? f0 + 84 : HIDD;
        float acc = 0.f;
        if (o < FI * NOUT) {
            int i2 = o / NOUT, oo = o % NOUT;
            for (int f = f0; f < f1; f++)
                acc += W[i2 * HIDD + f] * sS[f] * W2[f * NOUT + oo];
        } else {
            int oo = o - FI * NOUT;
            for (int f = f0; f < f1; f++)
                acc += (b[f] * sS[f] + sT[f]) * W2[f * NOUT + oo];
        }
        sRed[t] = acc;
    }
    __syncthreads();
    if (t < 42) {
        float acc = 0.f;
#pragma unroll
        for (int k = 0; k < 6; k++) acc += sRed[t * 6 + k];
        sMC[t] = (t < FI * NOUT) ? acc : acc + lb[t - FI * NOUT];
    }
    __syncthreads();

    // ---- Final: per-node head from shared chunk
    float2* out2 = (float2*)out;
    if (t < CH) {
        float p0 = sMC[FI * NOUT], p1 = sMC[FI * NOUT + 1];
        const float* ar = s + t * FI;
#pragma unroll
        for (int k = 0; k < FI; k++) {
            float v = ar[k];
            p0 += v * sMC[k * NOUT];
            p1 += v * sMC[k * NOUT + 1];
        }
        float l0 = fmaxf(p0, 0.f), l1 = fmaxf(p1, 0.f);
        float mx = fmaxf(l0, l1);
        float e0 = expf(l0 - mx), e1 = expf(l1 - mx);
        float inv = 1.f / (e0 + e1);
        out2[n0 + t] = make_float2(e0 * inv, e1 * inv);
    }
}

extern "C" void kernel_launch(void* const* d_in, const int* in_sizes, int n_in,
                              void* d_out, int out_size) {
    const float* X     = (const float*)d_in[0];   // node_feature [50000,20]
    const int*   ei    = (const int*)  d_in[1];   // edge_index   [2,E]
    const float* gcnW  = (const float*)d_in[2];   // [20,500]
    const float* gcnB  = (const float*)d_in[3];   // [500]
    const float* gamma = (const float*)d_in[4];   // [500]
    const float* beta  = (const float*)d_in[5];   // [500]
    const float* linW  = (const float*)d_in[6];   // [500,2]
    const float* linB  = (const float*)d_in[7];   // [2]
    float* out = (float*)d_out;                   // [NN*2 action_prob][500 rsu]

    int E = in_sizes[1] / 2;
    int nb  = (NN + 255) / 256;
    int eb  = (E + 255) / 256;
    int eb4 = (E / 4 + 255) / 256 + 1;

    k_deg<<<eb4, 256>>>(ei + E, E);
    k_prepX<<<nb, 256>>>(X);
    k_scatter<<<eb, 256>>>(ei, E);
    k_tail2<<<NB, 256>>>(gcnW, gcnB, gamma, beta, linW, linB, out);
}

// round 8
// speedup vs baseline: 1.2240x; 1.2240x over previous
#include <cuda_runtime.h>
#include <math.h>

#define NN    50000
#define FI    20
#define HIDD  500
#define NOUT  2
#define NPAIR 210            // upper-triangular (incl. diag) pairs of 20
#define BN_EPS 1e-5f
#define CH    250            // nodes per block in gather/stats (200 blocks)
#define NB    (NN / CH)
#define PAD   64             // padded-CSR width (deg ~ Poisson(16))
#define OVFC  4096           // overflow capacity (general-correctness fallback)

// ---- scratch (__device__ globals, zero-initialized; self-cleaning) ----
static __device__ int            g_cnt[NN];        // degree counter (build), zeroed in gather
static __device__ unsigned short g_slots[PAD * NN];// slot-major CSR: slots[j*NN+c]=row
static __device__ int            g_ovfn;           // overflow count (zeroed in k_prep)
static __device__ int2           g_ovf[OVFC];      // overflow (row,col) pairs
static __device__ float          g_dinv[NN];
static __device__ float4         g_Xs4[NN * 5];    // Xs = dinv[n] * X[n]
static __device__ float4         g_agg4[NN * 5];   // aggX = dinv * (sum + Xs)
static __device__ double         g_m[FI];          // column sums of aggX
static __device__ double         g_G[NPAIR];       // upper-tri Gram aggX^T aggX
static __device__ float          g_M2[FI * NOUT];  // folded 20x2 head matrix
static __device__ float          g_C[NOUT];        // folded bias

// K1: build padded CSR: for edge (r,c): slots[pos][c] = r  (int atomics only)
__global__ void __launch_bounds__(256) k_build(const int* __restrict__ ei, int E) {
    int t = blockIdx.x * blockDim.x + threadIdx.x;
    int e = 4 * t;
    if (e + 3 < E) {
        int4 r4 = *(const int4*)(ei + e);
        int4 c4 = *(const int4*)(ei + E + e);
        int rr[4] = {r4.x, r4.y, r4.z, r4.w};
        int cc[4] = {c4.x, c4.y, c4.z, c4.w};
#pragma unroll
        for (int k = 0; k < 4; k++) {
            int pos = atomicAdd(&g_cnt[cc[k]], 1);
            if (pos < PAD) g_slots[pos * NN + cc[k]] = (unsigned short)rr[k];
            else {
                int o = atomicAdd(&g_ovfn, 1);
                if (o < OVFC) g_ovf[o] = make_int2(rr[k], cc[k]);
            }
        }
    } else {
        for (int k = e; k < E; k++) {
            int r = ei[k], c = ei[E + k];
            int pos = atomicAdd(&g_cnt[c], 1);
            if (pos < PAD) g_slots[pos * NN + c] = (unsigned short)r;
            else {
                int o = atomicAdd(&g_ovfn, 1);
                if (o < OVFC) g_ovf[o] = make_int2(r, c);
            }
        }
    }
}

// K2: dinv = rsqrt(deg+1); Xs[n] = dinv[n]*X[n]  (keeps g_cnt for gather)
__global__ void __launch_bounds__(256) k_prepX(const float* __restrict__ X) {
    int n = blockIdx.x * blockDim.x + threadIdx.x;
    if (n >= NN) return;
    float d = rsqrtf((float)(g_cnt[n] + 1));
    g_dinv[n] = d;
    const float4* xr = (const float4*)(X + n * FI);
#pragma unroll
    for (int k = 0; k < 5; k++) {
        float4 v = xr[k];
        v.x *= d; v.y *= d; v.z *= d; v.w *= d;
        g_Xs4[n * 5 + k] = v;
    }
}

// K3: gather (no float atomics) + finalize aggX + stats. Self-cleans g_cnt.
__global__ void __launch_bounds__(256) k_gather(float dummy) {
    __shared__ float s[CH * 21];               // stride 21: conflict-free
    int t = threadIdx.x;                       // 256 threads (250 gather)
    int n0 = blockIdx.x * CH;
    int ovfn = g_ovfn;                         // 0 on this input

    if (t < CH) {
        int n = n0 + t;
        int deg = g_cnt[n];
        g_cnt[n] = 0;                          // self-clean for next replay
        float4 a0 = make_float4(0.f,0.f,0.f,0.f), a1 = a0, a2 = a0, a3 = a0, a4 = a0;
        int m = deg < PAD ? deg : PAD;
        for (int j = 0; j < m; j++) {
            int r = (int)g_slots[j * NN + n];  // coalesced across threads
            const float4* xs = g_Xs4 + r * 5;
            float4 v0 = __ldg(xs + 0), v1 = __ldg(xs + 1), v2 = __ldg(xs + 2),
                   v3 = __ldg(xs + 3), v4 = __ldg(xs + 4);
            a0.x += v0.x; a0.y += v0.y; a0.z += v0.z; a0.w += v0.w;
            a1.x += v1.x; a1.y += v1.y; a1.z += v1.z; a1.w += v1.w;
            a2.x += v2.x; a2.y += v2.y; a2.z += v2.z; a2.w += v2.w;
            a3.x += v3.x; a3.y += v3.y; a3.z += v3.z; a3.w += v3.w;
            a4.x += v4.x; a4.y += v4.y; a4.z += v4.z; a4.w += v4.w;
        }
        if (ovfn > 0) {                        // rare general-correctness path
            int L = ovfn < OVFC ? ovfn : OVFC;
            for (int o = 0; o < L; o++) {
                int2 rc = g_ovf[o];
                if (rc.y == n) {
                    const float4* xs = g_Xs4 + rc.x * 5;
                    float4 v0 = xs[0], v1 = xs[1], v2 = xs[2], v3 = xs[3], v4 = xs[4];
                    a0.x += v0.x; a0.y += v0.y; a0.z += v0.z; a0.w += v0.w;
                    a1.x += v1.x; a1.y += v1.y; a1.z += v1.z; a1.w += v1.w;
                    a2.x += v2.x; a2.y += v2.y; a2.z += v2.z; a2.w += v2.w;
                    a3.x += v3.x; a3.y += v3.y; a3.z += v3.z; a3.w += v3.w;
                    a4.x += v4.x; a4.y += v4.y; a4.z += v4.z; a4.w += v4.w;
                }
            }
        }
        // self term + dinv scaling
        float d = g_dinv[n];
        const float4* xsn = g_Xs4 + n * 5;
        float4 w0 = xsn[0], w1 = xsn[1], w2 = xsn[2], w3 = xsn[3], w4 = xsn[4];
        a0.x = d*(a0.x+w0.x); a0.y = d*(a0.y+w0.y); a0.z = d*(a0.z+w0.z); a0.w = d*(a0.w+w0.w);
        a1.x = d*(a1.x+w1.x); a1.y = d*(a1.y+w1.y); a1.z = d*(a1.z+w1.z); a1.w = d*(a1.w+w1.w);
        a2.x = d*(a2.x+w2.x); a2.y = d*(a2.y+w2.y); a2.z = d*(a2.z+w2.z); a2.w = d*(a2.w+w2.w);
        a3.x = d*(a3.x+w3.x); a3.y = d*(a3.y+w3.y); a3.z = d*(a3.z+w3.z); a3.w = d*(a3.w+w3.w);
        a4.x = d*(a4.x+w4.x); a4.y = d*(a4.y+w4.y); a4.z = d*(a4.z+w4.z); a4.w = d*(a4.w+w4.w);
        // publish: global (for k_final) + shared (for stats)
        float4* ag = g_agg4 + n * 5;
        ag[0] = a0; ag[1] = a1; ag[2] = a2; ag[3] = a3; ag[4] = a4;
        float* sr = s + t * 21;
        sr[0]=a0.x; sr[1]=a0.y; sr[2]=a0.z; sr[3]=a0.w;
        sr[4]=a1.x; sr[5]=a1.y; sr[6]=a1.z; sr[7]=a1.w;
        sr[8]=a2.x; sr[9]=a2.y; sr[10]=a2.z; sr[11]=a2.w;
        sr[12]=a3.x; sr[13]=a3.y; sr[14]=a3.z; sr[15]=a3.w;
        sr[16]=a4.x; sr[17]=a4.y; sr[18]=a4.z; sr[19]=a4.w;
    }
    __syncthreads();

    // stats: fp32 partials, double-atomic combine (as R5)
    if (t < FI) {
        float b0 = 0.f, b1 = 0.f;
        for (int n = 0; n < CH; n += 2) {
            b0 += s[n * 21 + t];
            b1 += s[(n + 1) * 21 + t];
        }
        atomicAdd(&g_m[t], (double)(b0 + b1));
    } else if (t < FI + NPAIR) {
        int p = t - FI, i = 0;
        while (p >= FI - i) { p -= FI - i; i++; }
        int j = i + p;
        float b0 = 0.f, b1 = 0.f;
        for (int n = 0; n < CH; n += 2) {
            b0 += s[n * 21 + i] * s[n * 21 + j];
            b1 += s[(n + 1) * 21 + i] * s[(n + 1) * 21 + j];
        }
        atomicAdd(&g_G[t - FI], (double)(b0 + b1));
    }
}

// K4 (1 block, 256 threads): fold BN into the head; emit rsu_embedding.
__global__ void __launch_bounds__(256) k_prep(
                       const float* __restrict__ W,      // gcn_W  [20,500]
                       const float* __restrict__ b,      // gcn_b  [500]
                       const float* __restrict__ gamma,  // [500]
                       const float* __restrict__ beta,   // [500]
                       const float* __restrict__ W2,     // lin_W  [500,2]
                       const float* __restrict__ lb,     // lin_b  [2]
                       float* __restrict__ out_rsu) {    // d_out + NN*NOUT
    __shared__ float  sW[FI * HIDD];   // 40 KB
    __shared__ float  sS[HIDD], sT[HIDD];
    __shared__ double smm[FI];
    __shared__ float  sGf[NPAIR];
    __shared__ float  sRed[42 * 6];
    int t = threadIdx.x;               // 256 threads
    for (int k = t; k < FI * HIDD; k += 256) sW[k] = W[k];
    if (t < FI)    { smm[t] = g_m[t];           g_m[t] = 0.0; }       // self-clean
    if (t < NPAIR) { sGf[t] = (float)g_G[t];    g_G[t] = 0.0; }       // self-clean
    if (t == 255)  g_ovfn = 0;                                        // self-clean
    __syncthreads();

    const float* a0 = (const float*)g_agg4;   // node 0 row
    for (int f = t; f < HIDD; f += 256) {
        float w[FI];
#pragma unroll
        for (int i2 = 0; i2 < FI; i2++) w[i2] = sW[i2 * HIDD + f];
        float bf = b[f];
        double su = 0.0;
#pragma unroll
        for (int i2 = 0; i2 < FI; i2++) su += smm[i2] * (double)w[i2];
        float suf = (float)su;
        float mean = (suf + (float)NN * bf) * (1.f / (float)NN);
        float q = 0.f;
        int p = 0;
#pragma unroll
        for (int i2 = 0; i2 < FI; i2++) {
            q += sGf[p++] * w[i2] * w[i2];
#pragma unroll
            for (int j2 = i2 + 1; j2 < FI; j2++)
                q += 2.f * sGf[p++] * w[i2] * w[j2];
        }
        float sumsq_over_n = q * (1.f / (float)NN)
                           + 2.f * bf * suf * (1.f / (float)NN) + bf * bf;
        float var = sumsq_over_n - mean * mean;
        float sc = gamma[f] * rsqrtf(var + BN_EPS);
        float tt = beta[f] - mean * sc;
        sS[f] = sc; sT[f] = tt;
        float u0 = 0.f;
#pragma unroll
        for (int i2 = 0; i2 < FI; i2++) u0 += a0[i2] * w[i2];
        out_rsu[f] = (u0 + bf) * sc + tt;
    }
    __syncthreads();

    if (t < 42 * 6) {                     // parallel fold of M2/C
        int o = t / 6, part = t % 6;
        int f0 = part * 84;
        int f1 = (f0 + 84 < HIDD) ? f0 + 84 : HIDD;
        float acc = 0.f;
        if (o < FI * NOUT) {
            int i2 = o / NOUT, oo = o % NOUT;
            for (int f = f0; f < f1; f++)
                acc += sW[i2 * HIDD + f] * sS[f] * W2[f * NOUT + oo];
        } else {
            int oo = o - FI * NOUT;
            for (int f = f0; f < f1; f++)
                acc += (b[f] * sS[f] + sT[f]) * W2[f * NOUT + oo];
        }
        sRed[t] = acc;
    }
    __syncthreads();
    if (t < 42) {
        float acc = 0.f;
#pragma unroll
        for (int k = 0; k < 6; k++) acc += sRed[t * 6 + k];
        if (t < FI * NOUT) g_M2[t] = acc;
        else               g_C[t - FI * NOUT] = acc + lb[t - FI * NOUT];
    }
}

// K5: per-node head: logits = relu(aggX[n].M2 + C); softmax over 2 classes
__global__ void __launch_bounds__(256) k_final(float* __restrict__ out) {
    __shared__ float sM[FI * NOUT];
    __shared__ float sC[NOUT];
    int t = threadIdx.x;
    if (t < FI * NOUT) sM[t] = g_M2[t];
    if (t < NOUT)      sC[t] = g_C[t];
    __syncthreads();
    int n = blockIdx.x * blockDim.x + t;
    if (n >= NN) return;
    float p0 = sC[0], p1 = sC[1];
    const float4* ar = (const float4*)(g_agg4 + n * 5);
#pragma unroll
    for (int k = 0; k < 5; k++) {
        float4 v = ar[k];
        p0 += v.x * sM[(4 * k + 0) * NOUT] + v.y * sM[(4 * k + 1) * NOUT]
            + v.z * sM[(4 * k + 2) * NOUT] + v.w * sM[(4 * k + 3) * NOUT];
        p1 += v.x * sM[(4 * k + 0) * NOUT + 1] + v.y * sM[(4 * k + 1) * NOUT + 1]
            + v.z * sM[(4 * k + 2) * NOUT + 1] + v.w * sM[(4 * k + 3) * NOUT + 1];
    }
    float l0 = fmaxf(p0, 0.f), l1 = fmaxf(p1, 0.f);
    float mx = fmaxf(l0, l1);
    float e0 = expf(l0 - mx), e1 = expf(l1 - mx);
    float inv = 1.f / (e0 + e1);
    out[2 * n + 0] = e0 * inv;
    out[2 * n + 1] = e1 * inv;
}

extern "C" void kernel_launch(void* const* d_in, const int* in_sizes, int n_in,
                              void* d_out, int out_size) {
    const float* X     = (const float*)d_in[0];   // node_feature [50000,20]
    const int*   ei    = (const int*)  d_in[1];   // edge_index   [2,E]
    const float* gcnW  = (const float*)d_in[2];   // [20,500]
    const float* gcnB  = (const float*)d_in[3];   // [500]
    const float* gamma = (const float*)d_in[4];   // [500]
    const float* beta  = (const float*)d_in[5];   // [500]
    const float* linW  = (const float*)d_in[6];   // [500,2]
    const float* linB  = (const float*)d_in[7];   // [2]
    float* out = (float*)d_out;                   // [NN*2 action_prob][500 rsu]

    int E = in_sizes[1] / 2;
    int nb  = (NN + 255) / 256;
    int eb4 = (E / 4 + 255) / 256 + 1;

    k_build<<<eb4, 256>>>(ei, E);
    k_prepX<<<nb, 256>>>(X);
    k_gather<<<NB, 256>>>(0.f);
    k_prep<<<1, 256>>>(gcnW, gcnB, gamma, beta, linW, linB, out + NN * NOUT);
    k_final<<<nb, 256>>>(out);
}